// round 16
// baseline (speedup 1.0000x reference)
#include <cuda_runtime.h>
#include <math.h>

#define NB 8

__constant__ float c_START_Y[NB] = {0.1f, 0.2f, 0.3f, 0.4f, 0.5f, 0.6f, 0.7f, 0.8f};
__constant__ float c_START_X[NB] = {0.8f, 0.7f, 0.6f, 0.5f, 0.4f, 0.3f, 0.2f, 0.1f};
__constant__ int   c_SIDE[NB]    = {1, 0, 1, 0, 1, 0, 1, 0};

#define MAX_B 4096
__device__ float g_params[NB * MAX_B * 5];

__device__ __forceinline__ float sigmoidf_(float v) {
    return 1.0f / (1.0f + __expf(-v));
}

// ---------------- f32x2 packed helpers (Blackwell) --------------------------
typedef unsigned long long ull;
__device__ __forceinline__ ull pk2(float x, float y) {
    ull r; asm("mov.b64 %0, {%1,%2};" : "=l"(r) : "f"(x), "f"(y)); return r;
}
__device__ __forceinline__ void upk2(float& x, float& y, ull v) {
    asm("mov.b64 {%0,%1}, %2;" : "=f"(x), "=f"(y) : "l"(v));
}
__device__ __forceinline__ ull fma2(ull a, ull b, ull c) {
    ull d; asm("fma.rn.f32x2 %0, %1, %2, %3;" : "=l"(d) : "l"(a), "l"(b), "l"(c)); return d;
}
__device__ __forceinline__ ull mul2(ull a, ull b) {
    ull d; asm("mul.rn.f32x2 %0, %1, %2;" : "=l"(d) : "l"(a), "l"(b)); return d;
}
__device__ __forceinline__ float ex2_(float v) {
    float r; asm("ex2.approx.ftz.f32 %0, %1;" : "=f"(r) : "f"(v)); return r;
}

// ---------------------------------------------------------------------------
// FUSED kernel (T = 256): one block = 64 rows of one image.
// Phase 1: full 8-blob MLP for this image (duplicated per block; W2 hits L1
// across blocks on the same SM). Phase 2: R15 multiplicative-recurrence splat,
// 4 passes x 16 rows, math byte-identical to the R15-passing kernel.
// grid = (4, B), block = 256.
// ---------------------------------------------------------------------------
__global__ void __launch_bounds__(256, 6) fused256(float* __restrict__ out,
                              const float* __restrict__ positions,
                              const float* __restrict__ W1, const float* __restrict__ b1,
                              const float* __restrict__ W2, const float* __restrict__ b2,
                              const float* __restrict__ W3, const float* __restrict__ b3,
                              const float* __restrict__ scale_ptr,
                              int B, int T, float invT)
{
    const int b   = blockIdx.y;
    const int tid = threadIdx.x;
    const int i   = tid >> 5;        // blob 0..7
    const int k   = tid & 31;        // hidden lo index (this thread owns k and k+32)

    __shared__ float sh_h[NB][64];
    __shared__ float sh_h2[NB][64];
    __shared__ float sh_bd[NB][5];
    __shared__ float spb[NB][5];                 // y, x, al, be, ga
    __shared__ float4 rowtab[64][NB];            // {K1, K0, cd, K2}
    __shared__ __align__(16) float qds[NB];
    __shared__ __align__(16) float rhos[NB];

    // ---- layer 1: 3 -> 64, relu (2 hidden units per thread) ----
    {
        const float* p = positions + (size_t)b * 6 + (c_SIDE[i] ? 0 : 3);
        float p0 = p[0] * 100.0f, p1 = p[1] * 100.0f, p2 = p[2] * 100.0f;
        const float* w1 = W1 + i * 192;
        float h0 = fmaf(p0, w1[k],      fmaf(p1, w1[64 + k],  fmaf(p2, w1[128 + k], b1[i * 64 + k])));
        float h1 = fmaf(p0, w1[32 + k], fmaf(p1, w1[96 + k],  fmaf(p2, w1[160 + k], b1[i * 64 + 32 + k])));
        sh_h[i][k]      = fmaxf(h0, 0.0f);
        sh_h[i][k + 32] = fmaxf(h1, 0.0f);
    }
    __syncthreads();

    // ---- layer 2: 64 -> 64, relu ----
    {
        const float* w2 = W2 + (size_t)i * 4096;
        float a0 = b2[i * 64 + k];
        float a1 = b2[i * 64 + 32 + k];
        #pragma unroll 8
        for (int hh = 0; hh < 64; hh++) {
            float hv = sh_h[i][hh];
            a0 = fmaf(hv, w2[hh * 64 + k],      a0);
            a1 = fmaf(hv, w2[hh * 64 + 32 + k], a1);
        }
        sh_h2[i][k]      = fmaxf(a0, 0.0f);
        sh_h2[i][k + 32] = fmaxf(a1, 0.0f);
    }
    __syncthreads();

    // ---- layer 3: 64 -> 5 ----
    if (k < 5) {
        const float* w3 = W3 + i * 320;
        float o0 = b3[i * 5 + k], o1 = 0.0f;
        #pragma unroll 8
        for (int hh = 0; hh < 64; hh += 2) {
            o0 = fmaf(sh_h2[i][hh],     w3[hh * 5 + k],       o0);
            o1 = fmaf(sh_h2[i][hh + 1], w3[(hh + 1) * 5 + k], o1);
        }
        sh_bd[i][k] = o0 + o1;
    }
    __syncthreads();

    // ---- blob-parameter epilogue ----
    if (tid < NB) {
        const int ii = tid;
        float bd0 = sh_bd[ii][0], bd1 = sh_bd[ii][1], bd2 = sh_bd[ii][2];
        float bd3 = sh_bd[ii][3], bd4 = sh_bd[ii][4];
        float scale = *scale_ptr;

        float y  = sigmoidf_(bd0) + c_START_Y[ii];
        float x  = sigmoidf_(bd1) + c_START_X[ii];
        float s  = (bd2 + 0.05f) * scale;
        float a  = 0.5f + sigmoidf_(bd3) * 1.5f;
        float th = sigmoidf_(bd4) * 3.14159265358979323846f;

        float sa = s * a + 1e-6f;
        float sb = s / (a + 1e-6f) + 1e-6f;
        float A  = 0.5f / (sa * sa);
        float Bq = 0.5f / (sb * sb);

        float sn = __sinf(th);          // th in [0, pi]
        float c  = __cosf(th);

        const float L = 1.4426950408889634f;
        float al = -L * (A * c * c + Bq * sn * sn);
        float be = -L * (A * sn * sn + Bq * c * c);
        float ga = -2.0f * L * (A - Bq) * c * sn;

        spb[ii][0] = y; spb[ii][1] = x; spb[ii][2] = al;
        spb[ii][3] = be; spb[ii][4] = ga;
        qds[ii]  = 4.0f * be * invT;
        rhos[ii] = exp2f(8.0f * be * invT * invT);   // in (0, 1]
    }
    __syncthreads();

    // ---- rowtab for this block's 64 rows ----
    #pragma unroll
    for (int e = tid; e < 64 * NB; e += 256) {
        int r  = e >> 3;
        int ii = e & 7;
        float y  = spb[ii][0], x = spb[ii][1];
        float al = spb[ii][2], be = spb[ii][3], ga = spb[ii][4];
        float rowc = ((float)(blockIdx.x * 64 + r) + 0.5f) * invT;
        float dy = rowc - y;
        float K2 = be;
        float K1 = fmaf(ga, dy, -2.0f * be * x);
        float mm = fmaf(al, dy, -(ga * x));
        float K0 = fmaf(mm, dy, be * x * x);
        float cd = fmaf(4.0f * K2 * invT, invT, 2.0f * K1 * invT);
        rowtab[r][ii] = make_float4(K1, K0, cd, K2);
    }
    __syncthreads();

    // ---- splat: 4 passes x 16 rows (R15 core, byte-identical math) ----
    const int lane   = tid & 31;
    const int wrp    = tid >> 5;                          // 0..7
    const int lane16 = lane & 15;
    const int seg    = lane16 * 16;

    const float w0 = ((float)seg + 0.5f) * invT;
    const float w1c = w0 + invT;

    const float4* qd4 = reinterpret_cast<const float4*>(qds);
    const float4* rh4 = reinterpret_cast<const float4*>(rhos);

    #pragma unroll 1
    for (int pass = 0; pass < 4; pass++) {
        const int rr  = pass * 16 + ((wrp << 1) | (lane >> 4));  // 0..63
        const int row = blockIdx.x * 64 + rr;

        ull img[8];
        #pragma unroll
        for (int kk = 0; kk < 8; kk++) img[kk] = 0ull;

        #pragma unroll
        for (int grp = 0; grp < 2; grp++) {
            const int base = grp * 4;
            float4 qv = qd4[grp];
            float4 rv = rh4[grp];
            float qdi[4] = {qv.x, qv.y, qv.z, qv.w};
            float rhi[4] = {rv.x, rv.y, rv.z, rv.w};

            ull g_[4], m_[4], r_[4];
            #pragma unroll
            for (int ii = 0; ii < 4; ii++) {
                float4 rt = rowtab[rr][base + ii];    // K1, K0, cd, K2
                float e0 = fmaf(fmaf(rt.w, w0, rt.x), w0, rt.y);
                float e1 = fmaf(fmaf(rt.w, w1c, rt.x), w1c, rt.y);
                float d0 = fminf(fmaf(qdi[ii], w0, rt.z), 126.0f);
                float d1 = fminf(fmaf(qdi[ii], w1c, rt.z), 126.0f);
                g_[ii] = pk2(ex2_(e0), ex2_(e1));
                m_[ii] = pk2(ex2_(d0), ex2_(d1));
                r_[ii] = pk2(rhi[ii], rhi[ii]);
            }

            #pragma unroll
            for (int kk = 0; kk < 8; kk++) {
                #pragma unroll
                for (int ii = 0; ii < 4; ii++)
                    img[kk] = fma2(img[kk], g_[ii], g_[ii]);   // blend order preserved
                if (kk < 7) {
                    #pragma unroll
                    for (int ii = 0; ii < 4; ii++) {
                        g_[ii] = mul2(g_[ii], m_[ii]);
                        m_[ii] = mul2(m_[ii], r_[ii]);
                    }
                }
            }
        }

        float* orow = out + ((size_t)b * T + row) * T + seg;
        #pragma unroll
        for (int j = 0; j < 4; j++) {
            float x0, x1, x2, x3;
            upk2(x0, x1, img[2 * j]);
            upk2(x2, x3, img[2 * j + 1]);
            reinterpret_cast<float4*>(orow)[j] = make_float4(x0, x1, x2, x3);
        }
    }
}

// ---------------------------------------------------------------------------
// Fallback path for T != 256: R15-passing encode + generic splat.
// ---------------------------------------------------------------------------
__global__ void encode_kernel(const float* __restrict__ positions,
                              const float* __restrict__ W1, const float* __restrict__ b1,
                              const float* __restrict__ W2, const float* __restrict__ b2,
                              const float* __restrict__ W3, const float* __restrict__ b3,
                              const float* __restrict__ scale_ptr, int B)
{
    const int i  = blockIdx.y;
    const int ty = threadIdx.y;
    const int k  = threadIdx.x;
    const int b  = blockIdx.x * 4 + ty;
    const bool valid = (b < B);

    __shared__ float sh_h[4][64];
    __shared__ float sh_bd[4][5];

    float h = 0.0f;
    if (valid) {
        const float* p = positions + (size_t)b * 6 + (c_SIDE[i] ? 0 : 3);
        float p0 = p[0] * 100.0f, p1 = p[1] * 100.0f, p2 = p[2] * 100.0f;
        const float* w1 = W1 + (size_t)i * 3 * 64;
        h = fmaf(p0, w1[k], fmaf(p1, w1[64 + k], fmaf(p2, w1[128 + k], b1[i * 64 + k])));
        h = fmaxf(h, 0.0f);
    }
    sh_h[ty][k] = h;
    __syncthreads();

    float acc = b2[i * 64 + k];
    {
        const float* w2 = W2 + (size_t)i * 64 * 64 + k;
        #pragma unroll 8
        for (int hh = 0; hh < 64; hh++)
            acc = fmaf(sh_h[ty][hh], w2[hh * 64], acc);
        acc = fmaxf(acc, 0.0f);
    }
    __syncthreads();
    sh_h[ty][k] = acc;
    __syncthreads();

    if (k < 5) {
        float o = b3[i * 5 + k];
        const float* w3 = W3 + (size_t)i * 64 * 5 + k;
        #pragma unroll 8
        for (int hh = 0; hh < 64; hh++)
            o = fmaf(sh_h[ty][hh], w3[hh * 5], o);
        sh_bd[ty][k] = o;
    }
    __syncthreads();

    if (k == 0 && valid) {
        float bd0 = sh_bd[ty][0], bd1 = sh_bd[ty][1], bd2 = sh_bd[ty][2];
        float bd3 = sh_bd[ty][3], bd4 = sh_bd[ty][4];
        float scale = *scale_ptr;

        float y  = sigmoidf_(bd0) + c_START_Y[i];
        float x  = sigmoidf_(bd1) + c_START_X[i];
        float s  = (bd2 + 0.05f) * scale;
        float a  = 0.5f + sigmoidf_(bd3) * 1.5f;
        float th = sigmoidf_(bd4) * 3.14159265358979323846f;

        float sa = s * a + 1e-6f;
        float sb = s / (a + 1e-6f) + 1e-6f;
        float A  = 0.5f / (sa * sa);
        float Bq = 0.5f / (sb * sb);

        float sn = __sinf(th);
        float c  = __cosf(th);

        const float L = 1.4426950408889634f;
        float al = -L * (A * c * c + Bq * sn * sn);
        float be = -L * (A * sn * sn + Bq * c * c);
        float ga = -2.0f * L * (A - Bq) * c * sn;

        float* o = g_params + ((size_t)i * B + b) * 5;
        o[0] = y; o[1] = x; o[2] = al; o[3] = be; o[4] = ga;
    }
}

__global__ void __launch_bounds__(256) splat_kernel(float* __restrict__ out,
                                                    int B, int T, float invT)
{
    const int b    = blockIdx.y;
    const int tid  = threadIdx.x;
    const int lane = tid & 31;
    const int r    = tid >> 5;
    const int row  = blockIdx.x * 8 + r;

    __shared__ float sp[NB * 5];
    if (tid < NB * 5) {
        int i = tid / 5, f = tid - i * 5;
        sp[tid] = g_params[((size_t)i * B + b) * 5 + f];
    }
    __syncthreads();
    if (row >= T) return;

    const float rowc = ((float)row + 0.5f) * invT;

    float K2[NB], K1[NB], K0[NB];
    #pragma unroll
    for (int i = 0; i < NB; i++) {
        float y  = sp[i * 5 + 0];
        float x  = sp[i * 5 + 1];
        float al = sp[i * 5 + 2];
        float be = sp[i * 5 + 3];
        float ga = sp[i * 5 + 4];
        float dy = rowc - y;
        K2[i] = be;
        K1[i] = fmaf(ga, dy, -2.0f * be * x);
        float m = fmaf(al, dy, -(ga * x));
        K0[i] = fmaf(m, dy, be * x * x);
    }

    float* orow = out + ((size_t)b * T + row) * T;
    const int nj = (T + 31) >> 5;

    for (int j = 0; j < nj; j++) {
        int col = lane + (j << 5);
        if (col >= T) break;
        float w = ((float)col + 0.5f) * invT;
        float img = 0.0f;
        #pragma unroll
        for (int i = 0; i < NB; i++) {
            float e = fmaf(fmaf(K2[i], w, K1[i]), w, K0[i]);
            float cur = ex2_(e);
            img = fmaf(img, cur, cur);
        }
        orow[col] = img;
    }
}

// ---------------------------------------------------------------------------
extern "C" void kernel_launch(void* const* d_in, const int* in_sizes, int n_in,
                              void* d_out, int out_size)
{
    const float* positions = (const float*)d_in[0];
    const float* W1 = (const float*)d_in[1];
    const float* b1 = (const float*)d_in[2];
    const float* W2 = (const float*)d_in[3];
    const float* b2 = (const float*)d_in[4];
    const float* W3 = (const float*)d_in[5];
    const float* b3 = (const float*)d_in[6];
    const float* scale = (const float*)d_in[n_in - 1];

    int B = in_sizes[0] / 6;
    int T = (int)(sqrt((double)out_size / (double)B) + 0.5);
    float invT = 1.0f / (float)T;

    if (T == 256) {
        dim3 fgrid(4, B);                 // 4 blocks x 64 rows per image
        fused256<<<fgrid, 256>>>((float*)d_out, positions,
                                 W1, b1, W2, b2, W3, b3, scale, B, T, invT);
    } else {
        int Bc = B > MAX_B ? MAX_B : B;
        dim3 egrid((Bc + 3) / 4, NB);
        dim3 eblock(64, 4);
        encode_kernel<<<egrid, eblock>>>(positions, W1, b1, W2, b2, W3, b3, scale, Bc);
        dim3 sgrid((T + 7) / 8, Bc);
        splat_kernel<<<sgrid, 256>>>((float*)d_out, Bc, T, invT);
    }
}

// round 17
// speedup vs baseline: 1.3041x; 1.3041x over previous
#include <cuda_runtime.h>
#include <math.h>

#define NB 8

__constant__ float c_START_Y[NB] = {0.1f, 0.2f, 0.3f, 0.4f, 0.5f, 0.6f, 0.7f, 0.8f};
__constant__ float c_START_X[NB] = {0.8f, 0.7f, 0.6f, 0.5f, 0.4f, 0.3f, 0.2f, 0.1f};
__constant__ int   c_SIDE[NB]    = {1, 0, 1, 0, 1, 0, 1, 0};

#define MAX_B 4096
__device__ float g_params[NB * MAX_B * 5];

__device__ __forceinline__ float sigmoidf_(float v) {
    return 1.0f / (1.0f + __expf(-v));
}

// ---------------- f32x2 packed helpers (Blackwell) --------------------------
typedef unsigned long long ull;
__device__ __forceinline__ ull pk2(float x, float y) {
    ull r; asm("mov.b64 %0, {%1,%2};" : "=l"(r) : "f"(x), "f"(y)); return r;
}
__device__ __forceinline__ void upk2(float& x, float& y, ull v) {
    asm("mov.b64 {%0,%1}, %2;" : "=f"(x), "=f"(y) : "l"(v));
}
__device__ __forceinline__ ull fma2(ull a, ull b, ull c) {
    ull d; asm("fma.rn.f32x2 %0, %1, %2, %3;" : "=l"(d) : "l"(a), "l"(b), "l"(c)); return d;
}
__device__ __forceinline__ ull mul2(ull a, ull b) {
    ull d; asm("mul.rn.f32x2 %0, %1, %2;" : "=l"(d) : "l"(a), "l"(b)); return d;
}
__device__ __forceinline__ float ex2_(float v) {
    float r; asm("ex2.approx.ftz.f32 %0, %1;" : "=f"(r) : "f"(v)); return r;
}

// ---------------------------------------------------------------------------
// Encode (R14-passing version: direct gmem weight loads, dual accumulators,
// __sinf/__cosf). block = (64, 4), grid = (B/4, NB).
// ---------------------------------------------------------------------------
__global__ void encode_kernel(const float* __restrict__ positions,
                              const float* __restrict__ W1, const float* __restrict__ b1,
                              const float* __restrict__ W2, const float* __restrict__ b2,
                              const float* __restrict__ W3, const float* __restrict__ b3,
                              const float* __restrict__ scale_ptr, int B)
{
    const int i  = blockIdx.y;
    const int ty = threadIdx.y;
    const int k  = threadIdx.x;
    const int b  = blockIdx.x * 4 + ty;
    const bool valid = (b < B);

    __shared__ float sh_h[4][64];
    __shared__ float sh_bd[4][5];

    float h = 0.0f;
    if (valid) {
        const float* p = positions + (size_t)b * 6 + (c_SIDE[i] ? 0 : 3);
        float p0 = p[0] * 100.0f, p1 = p[1] * 100.0f, p2 = p[2] * 100.0f;
        const float* w1 = W1 + (size_t)i * 3 * 64;
        h = fmaf(p0, w1[k], fmaf(p1, w1[64 + k], fmaf(p2, w1[128 + k], b1[i * 64 + k])));
        h = fmaxf(h, 0.0f);
    }
    sh_h[ty][k] = h;
    __syncthreads();

    float acc;
    {
        const float* w2 = W2 + (size_t)i * 64 * 64 + k;
        float a0 = b2[i * 64 + k], a1 = 0.0f;
        #pragma unroll 8
        for (int hh = 0; hh < 64; hh += 2) {
            a0 = fmaf(sh_h[ty][hh],     w2[hh * 64],        a0);
            a1 = fmaf(sh_h[ty][hh + 1], w2[(hh + 1) * 64],  a1);
        }
        acc = fmaxf(a0 + a1, 0.0f);
    }
    __syncthreads();
    sh_h[ty][k] = acc;
    __syncthreads();

    if (k < 5) {
        const float* w3 = W3 + (size_t)i * 64 * 5 + k;
        float o0 = b3[i * 5 + k], o1 = 0.0f;
        #pragma unroll 8
        for (int hh = 0; hh < 64; hh += 2) {
            o0 = fmaf(sh_h[ty][hh],     w3[hh * 5],       o0);
            o1 = fmaf(sh_h[ty][hh + 1], w3[(hh + 1) * 5], o1);
        }
        sh_bd[ty][k] = o0 + o1;
    }
    __syncthreads();

    if (k == 0 && valid) {
        float bd0 = sh_bd[ty][0], bd1 = sh_bd[ty][1], bd2 = sh_bd[ty][2];
        float bd3 = sh_bd[ty][3], bd4 = sh_bd[ty][4];
        float scale = *scale_ptr;

        float y  = sigmoidf_(bd0) + c_START_Y[i];
        float x  = sigmoidf_(bd1) + c_START_X[i];
        float s  = (bd2 + 0.05f) * scale;
        float a  = 0.5f + sigmoidf_(bd3) * 1.5f;
        float th = sigmoidf_(bd4) * 3.14159265358979323846f;

        float sa = s * a + 1e-6f;
        float sb = s / (a + 1e-6f) + 1e-6f;
        float A  = 0.5f / (sa * sa);
        float Bq = 0.5f / (sb * sb);

        float sn = __sinf(th);          // th in [0, pi]
        float c  = __cosf(th);

        const float L = 1.4426950408889634f;
        float al = -L * (A * c * c + Bq * sn * sn);
        float be = -L * (A * sn * sn + Bq * c * c);
        float ga = -2.0f * L * (A - Bq) * c * sn;

        float* o = g_params + ((size_t)i * B + b) * 5;
        o[0] = y; o[1] = x; o[2] = al; o[3] = be; o[4] = ga;
    }
}

// ---------------------------------------------------------------------------
// Splat (R15-passing version, byte-identical): multiplicative forward
// recurrence, step-outer / blob-group-inner, block = 128 threads = 8 rows,
// grid = (32, B).
// ---------------------------------------------------------------------------
__global__ void __launch_bounds__(128) splat_rec256(float* __restrict__ out,
                                                    int B, int T, float invT)
{
    const int b   = blockIdx.y;
    const int tid = threadIdx.x;

    __shared__ float  sp[NB * 5];
    __shared__ float4 rowtab[8][NB];             // {K1, K0, cd, K2}
    __shared__ __align__(16) float qds[NB];      // qd per blob
    __shared__ __align__(16) float rhos[NB];     // rho per blob

    if (tid < NB * 5) {
        int i = tid / 5, f = tid - i * 5;
        sp[tid] = g_params[((size_t)i * B + b) * 5 + f];
    }
    __syncthreads();

    if (tid < 64) {
        const int r = tid >> 3;          // row-in-block 0..7
        const int i = tid & 7;           // blob
        float y  = sp[i * 5 + 0];
        float x  = sp[i * 5 + 1];
        float al = sp[i * 5 + 2];
        float be = sp[i * 5 + 3];
        float ga = sp[i * 5 + 4];
        float rowc = ((float)(blockIdx.x * 8 + r) + 0.5f) * invT;
        float dy = rowc - y;
        float K2 = be;
        float K1 = fmaf(ga, dy, -2.0f * be * x);
        float mm = fmaf(al, dy, -(ga * x));
        float K0 = fmaf(mm, dy, be * x * x);
        // d(w) = e(w+2D) - e(w) = (4 K2 D) w + (4 K2 D^2 + 2 K1 D)
        float cd = fmaf(4.0f * K2 * invT, invT, 2.0f * K1 * invT);
        rowtab[r][i] = make_float4(K1, K0, cd, K2);
        if (r == 0) {
            qds[i]  = 4.0f * K2 * invT;
            rhos[i] = exp2f(8.0f * K2 * invT * invT);   // in (0, 1]
        }
    }
    __syncthreads();

    const int lane   = tid & 31;
    const int rr     = ((tid >> 5) << 1) | (lane >> 4);   // row-in-block 0..7
    const int lane16 = lane & 15;
    const int row    = blockIdx.x * 8 + rr;
    const int seg    = lane16 * 16;                       // first pixel of segment

    const float w0 = ((float)seg + 0.5f) * invT;
    const float w1 = w0 + invT;

    const float4* qd4 = reinterpret_cast<const float4*>(qds);
    const float4* rh4 = reinterpret_cast<const float4*>(rhos);

    ull img[8];
    #pragma unroll
    for (int k = 0; k < 8; k++) img[k] = 0ull;

    #pragma unroll
    for (int grp = 0; grp < 2; grp++) {
        const int base = grp * 4;
        float4 qv = qd4[grp];
        float4 rv = rh4[grp];
        float qdi[4] = {qv.x, qv.y, qv.z, qv.w};
        float rhi[4] = {rv.x, rv.y, rv.z, rv.w};

        ull g_[4], m_[4], r_[4];
        #pragma unroll
        for (int i = 0; i < 4; i++) {
            float4 rt = rowtab[rr][base + i];    // K1, K0, cd, K2
            float e0 = fmaf(fmaf(rt.w, w0, rt.x), w0, rt.y);
            float e1 = fmaf(fmaf(rt.w, w1, rt.x), w1, rt.y);
            float d0 = fminf(fmaf(qdi[i], w0, rt.z), 126.0f);
            float d1 = fminf(fmaf(qdi[i], w1, rt.z), 126.0f);
            g_[i] = pk2(ex2_(e0), ex2_(e1));
            m_[i] = pk2(ex2_(d0), ex2_(d1));
            r_[i] = pk2(rhi[i], rhi[i]);
        }

        #pragma unroll
        for (int k = 0; k < 8; k++) {
            #pragma unroll
            for (int i = 0; i < 4; i++)
                img[k] = fma2(img[k], g_[i], g_[i]);   // blend order preserved
            if (k < 7) {
                #pragma unroll
                for (int i = 0; i < 4; i++) {
                    g_[i] = mul2(g_[i], m_[i]);
                    m_[i] = mul2(m_[i], r_[i]);
                }
            }
        }
    }

    float* orow = out + ((size_t)b * T + row) * T + seg;
    #pragma unroll
    for (int j = 0; j < 4; j++) {
        float x0, x1, x2, x3;
        upk2(x0, x1, img[2 * j]);
        upk2(x2, x3, img[2 * j + 1]);
        reinterpret_cast<float4*>(orow)[j] = make_float4(x0, x1, x2, x3);
    }
}

// ---------------------------------------------------------------------------
// Generic fallback splat (round-2 kernel, known correct for any T).
// ---------------------------------------------------------------------------
__global__ void __launch_bounds__(256) splat_kernel(float* __restrict__ out,
                                                    int B, int T, float invT)
{
    const int b    = blockIdx.y;
    const int tid  = threadIdx.x;
    const int lane = tid & 31;
    const int r    = tid >> 5;
    const int row  = blockIdx.x * 8 + r;

    __shared__ float sp[NB * 5];
    if (tid < NB * 5) {
        int i = tid / 5, f = tid - i * 5;
        sp[tid] = g_params[((size_t)i * B + b) * 5 + f];
    }
    __syncthreads();
    if (row >= T) return;

    const float rowc = ((float)row + 0.5f) * invT;

    float K2[NB], K1[NB], K0[NB];
    #pragma unroll
    for (int i = 0; i < NB; i++) {
        float y  = sp[i * 5 + 0];
        float x  = sp[i * 5 + 1];
        float al = sp[i * 5 + 2];
        float be = sp[i * 5 + 3];
        float ga = sp[i * 5 + 4];
        float dy = rowc - y;
        K2[i] = be;
        K1[i] = fmaf(ga, dy, -2.0f * be * x);
        float m = fmaf(al, dy, -(ga * x));
        K0[i] = fmaf(m, dy, be * x * x);
    }

    float* orow = out + ((size_t)b * T + row) * T;
    const int nj = (T + 31) >> 5;

    for (int j = 0; j < nj; j++) {
        int col = lane + (j << 5);
        if (col >= T) break;
        float w = ((float)col + 0.5f) * invT;
        float img = 0.0f;
        #pragma unroll
        for (int i = 0; i < NB; i++) {
            float e = fmaf(fmaf(K2[i], w, K1[i]), w, K0[i]);
            float cur = ex2_(e);
            img = fmaf(img, cur, cur);
        }
        orow[col] = img;
    }
}

// ---------------------------------------------------------------------------
extern "C" void kernel_launch(void* const* d_in, const int* in_sizes, int n_in,
                              void* d_out, int out_size)
{
    const float* positions = (const float*)d_in[0];
    const float* W1 = (const float*)d_in[1];
    const float* b1 = (const float*)d_in[2];
    const float* W2 = (const float*)d_in[3];
    const float* b2 = (const float*)d_in[4];
    const float* W3 = (const float*)d_in[5];
    const float* b3 = (const float*)d_in[6];
    const float* scale = (const float*)d_in[n_in - 1];

    int B = in_sizes[0] / 6;
    if (B > MAX_B) B = MAX_B;
    int T = (int)(sqrt((double)out_size / (double)B) + 0.5);
    float invT = 1.0f / (float)T;

    dim3 egrid((B + 3) / 4, NB);
    dim3 eblock(64, 4);
    encode_kernel<<<egrid, eblock>>>(positions, W1, b1, W2, b2, W3, b3, scale, B);

    if (T == 256) {
        dim3 sgrid(32, B);                // 8 rows per 128-thread block
        splat_rec256<<<sgrid, 128>>>((float*)d_out, B, T, invT);
    } else {
        dim3 sgrid((T + 7) / 8, B);
        splat_kernel<<<sgrid, 256>>>((float*)d_out, B, T, invT);
    }
}